// round 8
// baseline (speedup 1.0000x reference)
#include <cuda_runtime.h>
#include <cuda_bf16.h>
#include <cstdint>

#define B_ 2
#define S_ 2048
#define D_ 1024
#define H_ 16
#define DK_ 64
#define OUT_ELEMS (B_*S_*D_)           /* 4194304  */
#define ATT_ELEMS (B_*H_*S_*S_)        /* 134217728 */

// ---------------- scratch (device globals; no allocation allowed) ----------
__device__ float g_Q[B_*H_*S_*DK_];    // [b][h][s][d], pre-scaled by 1/8
__device__ float g_K[B_*H_*S_*DK_];
__device__ float g_V[B_*H_*S_*DK_];
__device__ float g_C[B_*S_*D_];        // context, token-major

__device__ __forceinline__ uint32_t smem_u32(const void* p) {
    uint32_t a;
    asm("{ .reg .u64 t; cvta.to.shared.u64 t, %1; cvt.u32.u64 %0, t; }" : "=r"(a) : "l"(p));
    return a;
}

// ---------------- mma.sync primitives (baseline PTX, no 'a' features) ------
__device__ __forceinline__ void ldsm_x4(uint32_t (&r)[4], uint32_t addr) {
    asm volatile("ldmatrix.sync.aligned.m8n8.x4.shared.b16 {%0,%1,%2,%3}, [%4];"
        : "=r"(r[0]), "=r"(r[1]), "=r"(r[2]), "=r"(r[3]) : "r"(addr));
}
__device__ __forceinline__ void ldsm_x2(uint32_t (&r)[2], uint32_t addr) {
    asm volatile("ldmatrix.sync.aligned.m8n8.x2.shared.b16 {%0,%1}, [%2];"
        : "=r"(r[0]), "=r"(r[1]) : "r"(addr));
}
__device__ __forceinline__ void ldsm_x2t(uint32_t (&r)[2], uint32_t addr) {
    asm volatile("ldmatrix.sync.aligned.m8n8.x2.trans.shared.b16 {%0,%1}, [%2];"
        : "=r"(r[0]), "=r"(r[1]) : "r"(addr));
}
__device__ __forceinline__ void mma16816(float (&c)[4], const uint32_t (&a)[4],
                                         const uint32_t (&b)[2]) {
    asm volatile("mma.sync.aligned.m16n8k16.row.col.f32.bf16.bf16.f32 "
        "{%0,%1,%2,%3}, {%4,%5,%6,%7}, {%8,%9}, {%0,%1,%2,%3};"
        : "+f"(c[0]), "+f"(c[1]), "+f"(c[2]), "+f"(c[3])
        : "r"(a[0]), "r"(a[1]), "r"(a[2]), "r"(a[3]), "r"(b[0]), "r"(b[1]));
}
__device__ __forceinline__ uint32_t packbf(float lo, float hi) {
    uint32_t r;
    asm("cvt.rn.bf16x2.f32 %0, %1, %2;" : "=r"(r) : "f"(hi), "f"(lo));
    return r;
}
__device__ __forceinline__ float bf_round(float x) {
    return __bfloat162float(__float2bfloat16(x));
}
__device__ __forceinline__ void cvt4(uint2 &hi, uint2 &lo, float4 vv) {
    float v0 = vv.x, v1 = vv.y, v2 = vv.z, v3 = vv.w;
    __nv_bfloat16 h0 = __float2bfloat16(v0), h1 = __float2bfloat16(v1);
    __nv_bfloat16 h2 = __float2bfloat16(v2), h3 = __float2bfloat16(v3);
    __nv_bfloat162 hh0(h0, h1), hh1(h2, h3);
    __nv_bfloat162 ll0(__float2bfloat16(v0 - __bfloat162float(h0)),
                       __float2bfloat16(v1 - __bfloat162float(h1)));
    __nv_bfloat162 ll1(__float2bfloat16(v2 - __bfloat162float(h2)),
                       __float2bfloat16(v3 - __bfloat162float(h3)));
    hi = make_uint2(*(uint32_t*)&hh0, *(uint32_t*)&hh1);
    lo = make_uint2(*(uint32_t*)&ll0, *(uint32_t*)&ll1);
}

// ===========================================================================
// Split-bf16 tensor-core GEMM:  C[m,n] = scale * sum_k X[m,k] * W[n,k]
// mode 0: write head-major [b][h][s][d]; mode 1: plain row-major [m][n]
// ===========================================================================
#define PITCH 40
#define MAT_U (128*PITCH)
#define STAGE_U (4*MAT_U)
#define GT_SMEM (2*STAGE_U*2)

__device__ __forceinline__ size_t ymap(int m, int n, int mode) {
    if (mode == 0)
        return (((size_t)((m >> 11) * 16 + (n >> 6))) * 2048 + (m & 2047)) * 64 + (n & 63);
    return (size_t)m * 1024 + n;
}

__global__ __launch_bounds__(256) void mma_gemm(
    const float* __restrict__ X, const float* __restrict__ W,
    float* __restrict__ Y, float scale, int mode)
{
    extern __shared__ __nv_bfloat16 sh[];
    const uint32_t sh0 = smem_u32(sh);

    const int t = threadIdx.x;
    const int warp = t >> 5, lane = t & 31;
    const int bm = blockIdx.y * 128, bn = blockIdx.x * 128;
    const int wm = (warp >> 1) * 32;
    const int wn = (warp & 1) * 64;
    const int lr = t >> 3, lc = (t & 7) * 4;

    float4 ra[4], rb[4];
    float acc[2][8][4];
    #pragma unroll
    for (int mt = 0; mt < 2; mt++)
        #pragma unroll
        for (int nt = 0; nt < 8; nt++)
            #pragma unroll
            for (int j = 0; j < 4; j++) acc[mt][nt][j] = 0.f;

    const int r8 = lane & 7, tl = lane >> 3;
    const uint32_t a_row = (uint32_t)(wm + (tl & 1) * 8 + r8);
    const uint32_t a_col = (uint32_t)((tl >> 1) * 16);
    const uint32_t b_row = (uint32_t)(wn + r8);
    const uint32_t b_col = (uint32_t)((tl & 1) * 16);

    #define GEMM_LDG(c) do {                                                     \
        const float* xp = X + (size_t)(bm + lr) * 1024 + (c) * 32 + lc;          \
        const float* wp = W + (size_t)(bn + lr) * 1024 + (c) * 32 + lc;          \
        _Pragma("unroll")                                                        \
        for (int p = 0; p < 4; p++) {                                            \
            ra[p] = *(const float4*)(xp + (size_t)p * 32 * 1024);                \
            rb[p] = *(const float4*)(wp + (size_t)p * 32 * 1024);                \
        }                                                                        \
    } while (0)

    #define GEMM_STS(s) do {                                                     \
        __nv_bfloat16* Ah = sh + (s) * STAGE_U;                                  \
        __nv_bfloat16* Al = Ah + MAT_U;                                          \
        __nv_bfloat16* Bh = Ah + 2 * MAT_U;                                      \
        __nv_bfloat16* Bl = Ah + 3 * MAT_U;                                      \
        _Pragma("unroll")                                                        \
        for (int p = 0; p < 4; p++) {                                            \
            int row = lr + p * 32;                                               \
            uint2 hi, lo;                                                        \
            cvt4(hi, lo, ra[p]);                                                 \
            *(uint2*)&Ah[row * PITCH + lc] = hi;                                 \
            *(uint2*)&Al[row * PITCH + lc] = lo;                                 \
            cvt4(hi, lo, rb[p]);                                                 \
            *(uint2*)&Bh[row * PITCH + lc] = hi;                                 \
            *(uint2*)&Bl[row * PITCH + lc] = lo;                                 \
        }                                                                        \
    } while (0)

    #define GEMM_COMPUTE(s) do {                                                 \
        uint32_t Ahi = sh0 + (s) * STAGE_U * 2;                                  \
        uint32_t Alo = Ahi + MAT_U * 2;                                          \
        uint32_t Bhi = Ahi + 2 * MAT_U * 2;                                      \
        uint32_t Blo = Ahi + 3 * MAT_U * 2;                                      \
        _Pragma("unroll")                                                        \
        for (int ks = 0; ks < 2; ks++) {                                         \
            uint32_t ah[2][4], al[2][4];                                         \
            _Pragma("unroll")                                                    \
            for (int mt = 0; mt < 2; mt++) {                                     \
                uint32_t off = (a_row + mt * 16) * 80 + a_col + ks * 32;         \
                ldsm_x4(ah[mt], Ahi + off);                                      \
                ldsm_x4(al[mt], Alo + off);                                      \
            }                                                                    \
            _Pragma("unroll")                                                    \
            for (int nt = 0; nt < 8; nt++) {                                     \
                uint32_t boff = (b_row + nt * 8) * 80 + b_col + ks * 32;         \
                uint32_t bh[2], bl[2];                                           \
                ldsm_x2(bh, Bhi + boff);                                         \
                ldsm_x2(bl, Blo + boff);                                         \
                _Pragma("unroll")                                                \
                for (int mt = 0; mt < 2; mt++) {                                 \
                    mma16816(acc[mt][nt], ah[mt], bh);                           \
                    mma16816(acc[mt][nt], ah[mt], bl);                           \
                    mma16816(acc[mt][nt], al[mt], bh);                           \
                }                                                                \
            }                                                                    \
        }                                                                        \
    } while (0)

    GEMM_LDG(0);
    GEMM_STS(0);
    __syncthreads();
    for (int c = 0; c < 32; c++) {
        if (c < 31) GEMM_LDG(c + 1);
        GEMM_COMPUTE(c & 1);
        __syncthreads();
        if (c < 31) { GEMM_STS((c + 1) & 1); __syncthreads(); }
    }

    const int er = lane >> 2, ec = (lane & 3) * 2;
    #pragma unroll
    for (int mt = 0; mt < 2; mt++)
        #pragma unroll
        for (int nt = 0; nt < 8; nt++) {
            int m = bm + wm + mt * 16 + er;
            int n = bn + wn + nt * 8 + ec;
            float2 v0 = make_float2(acc[mt][nt][0] * scale, acc[mt][nt][1] * scale);
            float2 v1 = make_float2(acc[mt][nt][2] * scale, acc[mt][nt][3] * scale);
            *(float2*)&Y[ymap(m,     n, mode)] = v0;
            *(float2*)&Y[ymap(m + 8, n, mode)] = v1;
        }
}

// ===========================================================================
// Tensor-core attention (R5 config: 256 thr, 4q x 2k warps, 64-key chunks,
// in-loop split-bf16 conversion) + K/V register prefetch + FUSED rescale.
// Writes NORMALIZED attn weights and normalized context.
// ===========================================================================
#define AQHI 0
#define AQLO 18432
#define AKHI 36864
#define AKLO 46080
#define AVHI 55296
#define AVLO 64512
#define ALP  73728
#define AMSK 74752
#define AT_SMEM 75008
#define APB 144                       /* bytes per 72-bf16 row */

__global__ __launch_bounds__(256, 1) void attn_mma(
    const float* __restrict__ Qh, const float* __restrict__ Kh,
    const float* __restrict__ Vh, const int* __restrict__ mask,
    float* __restrict__ attn, float* __restrict__ Ctx)
{
    extern __shared__ char ash[];
    const uint32_t s0 = smem_u32(ash);
    float* Lpart = (float*)(ash + ALP);
    int*   Msk   = (int*)(ash + AMSK);

    const int t = threadIdx.x, warp = t >> 5, lane = t & 31;
    const int qw = warp >> 1, kw = warp & 1;
    const int q0 = blockIdx.x * 128, h = blockIdx.y, b = blockIdx.z;
    const int bh = b * H_ + h;
    const float* Qb = Qh + (size_t)bh * S_ * 64;
    const float* Kb = Kh + (size_t)bh * S_ * 64;
    const float* Vb = Vh + (size_t)bh * S_ * 64;

    Lpart[t] = 0.f;

    // ---- load Q tile (128x64) -> Qhi/Qlo ----
    {
        const int lr = t >> 3, lc = (t & 7) * 8;
        #pragma unroll
        for (int p = 0; p < 4; p++) {
            int row = lr + 32 * p;
            const float* src = Qb + (size_t)(q0 + row) * 64 + lc;
            uint2 hi, lo;
            cvt4(hi, lo, *(const float4*)src);
            *(uint2*)(ash + AQHI + row * APB + lc * 2)     = hi;
            *(uint2*)(ash + AQLO + row * APB + lc * 2)     = lo;
            cvt4(hi, lo, *(const float4*)(src + 4));
            *(uint2*)(ash + AQHI + row * APB + lc * 2 + 8) = hi;
            *(uint2*)(ash + AQLO + row * APB + lc * 2 + 8) = lo;
        }
    }

    const int r8 = lane & 7, tl = lane >> 3;
    const int er = lane >> 2, ec = (lane & 3) * 2;
    const uint32_t a_roff = (uint32_t)((qw * 32 + (tl & 1) * 8 + r8) * APB + (tl >> 1) * 16);
    const uint32_t b_roff = (uint32_t)((kw * 32 + r8) * APB + (tl & 1) * 16);
    const uint32_t v_roff = (uint32_t)((kw * 32 + (tl & 1) * 8 + r8) * APB);
    const int lr = t >> 3, lc = (t & 7) * 8;

    float4 fk[4], fv[4];
    int pm = 0;

    // prefetch chunk c into registers
    #define AT_LDG(c) do {                                                       \
        int kb = (c) * 64;                                                       \
        const float* sk0 = Kb + (size_t)(kb + lr) * 64 + lc;                     \
        const float* sv0 = Vb + (size_t)(kb + lr) * 64 + lc;                     \
        fk[0] = *(const float4*)sk0;       fk[1] = *(const float4*)(sk0 + 4);    \
        fk[2] = *(const float4*)(sk0 + 32*64); fk[3] = *(const float4*)(sk0 + 32*64 + 4); \
        fv[0] = *(const float4*)sv0;       fv[1] = *(const float4*)(sv0 + 4);    \
        fv[2] = *(const float4*)(sv0 + 32*64); fv[3] = *(const float4*)(sv0 + 32*64 + 4); \
        if (t < 64) pm = mask[b * S_ + kb + t];                                  \
    } while (0)

    AT_LDG(0);

    float oacc[2][8][4];
    #pragma unroll
    for (int mt = 0; mt < 2; mt++)
        #pragma unroll
        for (int nt = 0; nt < 8; nt++)
            #pragma unroll
            for (int j = 0; j < 4; j++) oacc[mt][nt][j] = 0.f;

    for (int c = 0; c < 32; c++) {
        const int kb = c * 64;
        __syncthreads();               // prev chunk compute done (and Q/Lpart init)

        // ---- store prefetched K,V (convert to split-bf16) + mask ----
        {
            #pragma unroll
            for (int p = 0; p < 2; p++) {
                int row = lr + 32 * p;
                uint2 hi, lo;
                cvt4(hi, lo, fk[2*p]);
                *(uint2*)(ash + AKHI + row * APB + lc * 2)     = hi;
                *(uint2*)(ash + AKLO + row * APB + lc * 2)     = lo;
                cvt4(hi, lo, fk[2*p + 1]);
                *(uint2*)(ash + AKHI + row * APB + lc * 2 + 8) = hi;
                *(uint2*)(ash + AKLO + row * APB + lc * 2 + 8) = lo;
                cvt4(hi, lo, fv[2*p]);
                *(uint2*)(ash + AVHI + row * APB + lc * 2)     = hi;
                *(uint2*)(ash + AVLO + row * APB + lc * 2)     = lo;
                cvt4(hi, lo, fv[2*p + 1]);
                *(uint2*)(ash + AVHI + row * APB + lc * 2 + 8) = hi;
                *(uint2*)(ash + AVLO + row * APB + lc * 2 + 8) = lo;
            }
            if (t < 64) Msk[t] = pm;
        }
        if (c < 31) AT_LDG(c + 1);     // overlap next loads with this compute
        __syncthreads();

        // ---- S = Q K^T (32q x 32k per warp), split-bf16 3-term ----
        float sc[2][4][4];
        #pragma unroll
        for (int mt = 0; mt < 2; mt++)
            #pragma unroll
            for (int nf = 0; nf < 4; nf++)
                #pragma unroll
                for (int j = 0; j < 4; j++) sc[mt][nf][j] = 0.f;

        #pragma unroll
        for (int ks = 0; ks < 4; ks++) {
            uint32_t qh_[2][4], ql_[2][4];
            #pragma unroll
            for (int mt = 0; mt < 2; mt++) {
                uint32_t off = a_roff + mt * 16 * APB + ks * 32;
                ldsm_x4(qh_[mt], s0 + AQHI + off);
                ldsm_x4(ql_[mt], s0 + AQLO + off);
            }
            #pragma unroll
            for (int nf = 0; nf < 4; nf++) {
                uint32_t boff = b_roff + nf * 8 * APB + ks * 32;
                uint32_t kh_[2], kl_[2];
                ldsm_x2(kh_, s0 + AKHI + boff);
                ldsm_x2(kl_, s0 + AKLO + boff);
                #pragma unroll
                for (int mt = 0; mt < 2; mt++) {
                    mma16816(sc[mt][nf], qh_[mt], kh_);
                    mma16816(sc[mt][nf], qh_[mt], kl_);
                    mma16816(sc[mt][nf], ql_[mt], kh_);
                }
            }
        }

        // ---- epilogue: mask+exp, row sums, attn store (unnormalized), P frags ----
        uint32_t phi[2][2][4], plo[2][2][4];
        #pragma unroll
        for (int mt = 0; mt < 2; mt++) {
            float rs0 = 0.f, rs1 = 0.f;
            #pragma unroll
            for (int nf = 0; nf < 4; nf++) {
                int col = kw * 32 + nf * 8 + ec;
                int m0 = Msk[col], m1 = Msk[col + 1];
                float p00 = m0 ? __expf(sc[mt][nf][0]) : 0.f;
                float p01 = m1 ? __expf(sc[mt][nf][1]) : 0.f;
                float p10 = m0 ? __expf(sc[mt][nf][2]) : 0.f;
                float p11 = m1 ? __expf(sc[mt][nf][3]) : 0.f;
                rs0 += p00 + p01; rs1 += p10 + p11;
                if (attn) {
                    int q = q0 + qw * 32 + mt * 16 + er;
                    size_t ro = ((size_t)bh * S_ + q) * S_ + kb + col;
                    *(float2*)&attn[ro]          = make_float2(p00, p01);
                    *(float2*)&attn[ro + 8 * S_] = make_float2(p10, p11);
                }
                int kf = nf >> 1, hf = (nf & 1) * 2;
                float h00 = bf_round(p00), h01 = bf_round(p01);
                float h10 = bf_round(p10), h11 = bf_round(p11);
                phi[mt][kf][hf]     = packbf(h00, h01);
                phi[mt][kf][hf + 1] = packbf(h10, h11);
                plo[mt][kf][hf]     = packbf(p00 - h00, p01 - h01);
                plo[mt][kf][hf + 1] = packbf(p10 - h10, p11 - h11);
            }
            rs0 += __shfl_xor_sync(0xffffffffu, rs0, 1);
            rs0 += __shfl_xor_sync(0xffffffffu, rs0, 2);
            rs1 += __shfl_xor_sync(0xffffffffu, rs1, 1);
            rs1 += __shfl_xor_sync(0xffffffffu, rs1, 2);
            if ((lane & 3) == 0) {
                int q = qw * 32 + mt * 16 + er;
                Lpart[kw * 128 + q]     += rs0;
                Lpart[kw * 128 + q + 8] += rs1;
            }
        }

        // ---- O += P V (keys slice of this warp), split 3-term ----
        #pragma unroll
        for (int kf = 0; kf < 2; kf++) {
            #pragma unroll
            for (int nf2 = 0; nf2 < 8; nf2++) {
                uint32_t voff = v_roff + kf * 16 * APB + nf2 * 16;
                uint32_t vh_[2], vl_[2];
                ldsm_x2t(vh_, s0 + AVHI + voff);
                ldsm_x2t(vl_, s0 + AVLO + voff);
                #pragma unroll
                for (int mt = 0; mt < 2; mt++) {
                    mma16816(oacc[mt][nf2], phi[mt][kf], vh_);
                    mma16816(oacc[mt][nf2], phi[mt][kf], vl_);
                    mma16816(oacc[mt][nf2], plo[mt][kf], vh_);
                }
            }
        }
    }

    // ---- reduce O across the 2 k-warps via smem, normalize, write ----
    __syncthreads();
    float* Ored = (float*)(ash + AKHI);        // 128 x 68 f32, fits in K/V area
    if (kw == 1) {
        #pragma unroll
        for (int mt = 0; mt < 2; mt++)
            #pragma unroll
            for (int nf2 = 0; nf2 < 8; nf2++) {
                int q = qw * 32 + mt * 16 + er, d = nf2 * 8 + ec;
                *(float2*)&Ored[q * 68 + d]       = make_float2(oacc[mt][nf2][0], oacc[mt][nf2][1]);
                *(float2*)&Ored[(q + 8) * 68 + d] = make_float2(oacc[mt][nf2][2], oacc[mt][nf2][3]);
            }
    }
    __syncthreads();
    if (kw == 0) {
        #pragma unroll
        for (int mt = 0; mt < 2; mt++) {
            int qA = qw * 32 + mt * 16 + er;
            float invA = 1.f / (Lpart[qA] + Lpart[128 + qA]);
            float invB = 1.f / (Lpart[qA + 8] + Lpart[128 + qA + 8]);
            #pragma unroll
            for (int nf2 = 0; nf2 < 8; nf2++) {
                int d = nf2 * 8 + ec;
                float2 oA = *(float2*)&Ored[qA * 68 + d];
                float2 oB = *(float2*)&Ored[(qA + 8) * 68 + d];
                oA.x = (oA.x + oacc[mt][nf2][0]) * invA;
                oA.y = (oA.y + oacc[mt][nf2][1]) * invA;
                oB.x = (oB.x + oacc[mt][nf2][2]) * invB;
                oB.y = (oB.y + oacc[mt][nf2][3]) * invB;
                size_t oo = ((size_t)b * S_ + q0 + qA) * D_ + h * 64 + d;
                *(float2*)&Ctx[oo]          = oA;
                *(float2*)&Ctx[oo + 8 * D_] = oB;
            }
        }
    }

    // ---- FUSED rescale: normalize this CTA's 128x2048 attn slab ----
    __syncthreads();                   // all attn writes + Lpart sums visible
    if (attn) {
        const size_t slab = ((size_t)bh * S_ + q0) * S_;
        #pragma unroll 1
        for (int rr = 0; rr < 128; rr++) {
            float inv = 1.0f / (Lpart[rr] + Lpart[128 + rr]);
            float4* p = (float4*)(attn + slab + (size_t)rr * S_);
            float4 v0 = p[t], v1 = p[t + 256];
            v0.x *= inv; v0.y *= inv; v0.z *= inv; v0.w *= inv;
            v1.x *= inv; v1.y *= inv; v1.z *= inv; v1.w *= inv;
            p[t] = v0; p[t + 256] = v1;
        }
    }
}

// ===========================================================================
extern "C" void kernel_launch(void* const* d_in, const int* in_sizes, int n_in,
                              void* d_out, int out_size)
{
    const float* query = (const float*)d_in[0];
    const float* key   = (const float*)d_in[1];
    const float* value = (const float*)d_in[2];
    const int*   mask  = (const int*)d_in[3];
    const float* W_Q   = (const float*)d_in[4];
    const float* W_K   = (const float*)d_in[5];
    const float* W_V   = (const float*)d_in[6];
    const float* W_O   = (const float*)d_in[7];

    float* out = (float*)d_out;
    bool hasAttn = (out_size >= OUT_ELEMS + ATT_ELEMS);
    float* attn = hasAttn ? (out + OUT_ELEMS) : nullptr;

    float *gq, *gk, *gv, *gc;
    cudaGetSymbolAddress((void**)&gq, g_Q);
    cudaGetSymbolAddress((void**)&gk, g_K);
    cudaGetSymbolAddress((void**)&gv, g_V);
    cudaGetSymbolAddress((void**)&gc, g_C);

    cudaFuncSetAttribute((const void*)attn_mma,
                         cudaFuncAttributeMaxDynamicSharedMemorySize, AT_SMEM);
    cudaFuncSetAttribute((const void*)mma_gemm,
                         cudaFuncAttributeMaxDynamicSharedMemorySize, GT_SMEM);

    dim3 gg(8, 32);   // N/128 x M/128
    mma_gemm<<<gg, 256, GT_SMEM>>>(query, W_Q, gq, 0.125f, 0);
    mma_gemm<<<gg, 256, GT_SMEM>>>(key,   W_K, gk, 1.0f,   0);
    mma_gemm<<<gg, 256, GT_SMEM>>>(value, W_V, gv, 1.0f,   0);
    attn_mma<<<dim3(16, 16, 2), 256, AT_SMEM>>>(gq, gk, gv, mask, attn, gc);
    mma_gemm<<<gg, 256, GT_SMEM>>>(gc, W_O, out, 1.0f, 1);
}